// round 2
// baseline (speedup 1.0000x reference)
#include <cuda_runtime.h>
#include <math.h>

#define N_TOK 2000
#define C_DIM 256
#define C3    768
#define H_NUM 8
#define HD    32

// ---------------- scratch (static device globals; no allocation) ----------------
static __device__ float g_yc[N_TOK * C3];           // qkv_cls  [2000,768]
static __device__ float g_yr[N_TOK * C3];           // qkv_reg
static __device__ float g_qnc[N_TOK * C_DIM];       // normalized q_cls (head-major cols)
static __device__ float g_knc[N_TOK * C_DIM];
static __device__ float g_qnr[N_TOK * C_DIM];
static __device__ float g_knr[N_TOK * C_DIM];
static __device__ float g_vn [N_TOK * C_DIM];       // normalized v_cls
static __device__ float g_S  [16ULL * N_TOK * N_TOK]; // [branch(2)][head(8)][i][j]; cls half becomes attn in-place
static __device__ float g_raw[(size_t)N_TOK * N_TOK]; // vn . vn^T  (= 8 * raw_mean)

// ---------------- reductions ----------------
__device__ __forceinline__ float warpMax(float v) {
    #pragma unroll
    for (int o = 16; o; o >>= 1) v = fmaxf(v, __shfl_xor_sync(0xffffffffu, v, o));
    return v;
}
__device__ __forceinline__ float warpSum(float v) {
    #pragma unroll
    for (int o = 16; o; o >>= 1) v += __shfl_xor_sync(0xffffffffu, v, o);
    return v;
}
__device__ float blockReduceMax(float v, float* red) {
    int w = threadIdx.x >> 5, l = threadIdx.x & 31;
    v = warpMax(v);
    if (l == 0) red[w] = v;
    __syncthreads();
    if (w == 0) {
        float x = (l < (int)(blockDim.x >> 5)) ? red[l] : -1e30f;
        x = warpMax(x);
        if (l == 0) red[0] = x;
    }
    __syncthreads();
    float r = red[0];
    __syncthreads();
    return r;
}
__device__ float blockReduceSum(float v, float* red) {
    int w = threadIdx.x >> 5, l = threadIdx.x & 31;
    v = warpSum(v);
    if (l == 0) red[w] = v;
    __syncthreads();
    if (w == 0) {
        float x = (l < (int)(blockDim.x >> 5)) ? red[l] : 0.f;
        x = warpSum(x);
        if (l == 0) red[0] = x;
    }
    __syncthreads();
    float r = red[0];
    __syncthreads();
    return r;
}

// ---------------- GEMM NN:  C[M,N] = A[M,K] * B[K,N]  (64x64 tile, 4x4/thread) ----------------
__global__ void sgemm_nn(const float* __restrict__ A, const float* __restrict__ B,
                         float* __restrict__ C, int M, int Nn, int K,
                         int lda, int ldb, int ldc) {
    __shared__ float As[64][33];
    __shared__ float Bs[32][65];
    int tid = threadIdx.x;
    int tx = tid & 15, ty = tid >> 4;
    int m0 = blockIdx.y * 64, n0 = blockIdx.x * 64;
    float acc[4][4] = {};
    for (int k0 = 0; k0 < K; k0 += 32) {
        #pragma unroll
        for (int p = 0; p < 8; ++p) {
            int idx = tid + p * 256;
            int r = idx >> 5, k = idx & 31;
            As[r][k] = (m0 + r < M) ? A[(size_t)(m0 + r) * lda + k0 + k] : 0.f;
            int kk = idx >> 6, nn = idx & 63;
            if (p < 4) { /* 32x64 = 2048 -> 8 passes also fills, but kk<32 check */ }
            if (kk < 32)
                Bs[kk][nn] = (n0 + nn < Nn) ? B[(size_t)(k0 + kk) * ldb + n0 + nn] : 0.f;
        }
        __syncthreads();
        #pragma unroll
        for (int k = 0; k < 32; ++k) {
            float ra[4], rb[4];
            #pragma unroll
            for (int x = 0; x < 4; ++x) { ra[x] = As[ty * 4 + x][k]; rb[x] = Bs[k][tx * 4 + x]; }
            #pragma unroll
            for (int mi = 0; mi < 4; ++mi)
                #pragma unroll
                for (int ni = 0; ni < 4; ++ni) acc[mi][ni] += ra[mi] * rb[ni];
        }
        __syncthreads();
    }
    #pragma unroll
    for (int mi = 0; mi < 4; ++mi) {
        int gm = m0 + ty * 4 + mi;
        if (gm >= M) continue;
        #pragma unroll
        for (int ni = 0; ni < 4; ++ni) {
            int gn = n0 + tx * 4 + ni;
            if (gn < Nn) C[(size_t)gm * ldc + gn] = acc[mi][ni];
        }
    }
}

// ---------------- batched GEMM NT:  C[M,N] = alpha * A[M,K] * B[N,K]^T ----------------
__global__ void sgemm_nt(const float* __restrict__ Abase, const float* __restrict__ Bbase,
                         float* __restrict__ Cbase,
                         int M, int Nn, int K, int lda, int ldb, int ldc,
                         int aOffZ, int bOffZ, long long cStrideZ, float alpha) {
    const float* A = Abase + (size_t)blockIdx.z * aOffZ;
    const float* B = Bbase + (size_t)blockIdx.z * bOffZ;
    float* C = Cbase + (size_t)blockIdx.z * cStrideZ;
    __shared__ float As[64][33];
    __shared__ float Bs[64][33];
    int tid = threadIdx.x;
    int tx = tid & 15, ty = tid >> 4;
    int m0 = blockIdx.y * 64, n0 = blockIdx.x * 64;
    float acc[4][4] = {};
    for (int k0 = 0; k0 < K; k0 += 32) {
        #pragma unroll
        for (int p = 0; p < 8; ++p) {
            int idx = tid + p * 256;
            int r = idx >> 5, k = idx & 31;
            As[r][k] = (m0 + r < M) ? A[(size_t)(m0 + r) * lda + k0 + k] : 0.f;
            Bs[r][k] = (n0 + r < Nn) ? B[(size_t)(n0 + r) * ldb + k0 + k] : 0.f;
        }
        __syncthreads();
        #pragma unroll
        for (int k = 0; k < 32; ++k) {
            float ra[4], rb[4];
            #pragma unroll
            for (int x = 0; x < 4; ++x) { ra[x] = As[ty * 4 + x][k]; rb[x] = Bs[tx * 4 + x][k]; }
            #pragma unroll
            for (int mi = 0; mi < 4; ++mi)
                #pragma unroll
                for (int ni = 0; ni < 4; ++ni) acc[mi][ni] += ra[mi] * rb[ni];
        }
        __syncthreads();
    }
    #pragma unroll
    for (int mi = 0; mi < 4; ++mi) {
        int gm = m0 + ty * 4 + mi;
        if (gm >= M) continue;
        #pragma unroll
        for (int ni = 0; ni < 4; ++ni) {
            int gn = n0 + tx * 4 + ni;
            if (gn < Nn) C[(size_t)gm * ldc + gn] = alpha * acc[mi][ni];
        }
    }
}

// ---------------- per-head L2 normalize + x_ori copy ----------------
__device__ __forceinline__ float normed_val(const float* __restrict__ src, int base, int t) {
    float v = src[base + t];
    float ss = warpSum(v * v);          // warp == one 32-dim head segment
    return v / (sqrtf(ss) + 1e-8f);
}
__global__ void normalize_kernel(const float* __restrict__ yc, const float* __restrict__ yr,
                                 float* __restrict__ out) {
    int n = blockIdx.x;
    int t = threadIdx.x;                // 256 threads, 8 warps == 8 heads
    int b = n * C3;
    g_qnc[n * C_DIM + t] = normed_val(yc, b + 0,   t);
    g_knc[n * C_DIM + t] = normed_val(yc, b + 256, t);
    g_vn [n * C_DIM + t] = normed_val(yc, b + 512, t);
    g_qnr[n * C_DIM + t] = normed_val(yr, b + 0,   t);
    g_knr[n * C_DIM + t] = normed_val(yr, b + 256, t);
    out[(size_t)n * 512 + 256 + t] = yc[b + 512 + t];   // x_ori half of x_out
}

// ---------------- softmax + combine + mask + sim_round2 (one CTA per row) ----------------
__global__ void softmax_combine(float* __restrict__ S, const float* __restrict__ raw,
                                float* __restrict__ out_sim) {
    __shared__ float scls[N_TOK];
    __shared__ float sreg[N_TOK];
    __shared__ float simr[N_TOK];
    __shared__ float red[32];
    int i = blockIdx.x;
    int t = threadIdx.x;
    for (int j = t; j < N_TOK; j += 256) simr[j] = 0.f;
    __syncthreads();
    int bs = (i / 10) * 10;
    for (int h = 0; h < H_NUM; ++h) {
        float* rowc = S + ((size_t)h * N_TOK + i) * N_TOK;
        float* rowr = S + ((size_t)(H_NUM + h) * N_TOK + i) * N_TOK;
        float mc = -1e30f, mr = -1e30f;
        for (int j = t; j < N_TOK; j += 256) {
            float a = rowc[j], b = rowr[j];
            scls[j] = a; sreg[j] = b;
            mc = fmaxf(mc, a); mr = fmaxf(mr, b);
        }
        mc = blockReduceMax(mc, red);
        mr = blockReduceMax(mr, red);
        float sc = 0.f, sr = 0.f;
        for (int j = t; j < N_TOK; j += 256) {
            sc += __expf(scls[j] - mc);
            sr += __expf(sreg[j] - mr);
        }
        sc = blockReduceSum(sc, red);
        sr = blockReduceSum(sr, red);
        float ic = 1.f / sc, ir = 1.f / sr;
        for (int j = t; j < N_TOK; j += 256) {
            float pc = __expf(scls[j] - mc) * ic;
            float pr = __expf(sreg[j] - mr) * ir;
            float a = 0.5f * (pc + pr);
            bool keep = (j == i) || (j < bs) || (j >= bs + 9);
            a = keep ? a : 0.f;
            rowc[j] = a;                 // attn written in-place over cls scores
            simr[j] += a;                // each thread owns its j's -> no race
        }
        __syncthreads();
    }
    // sim_round2
    float m = -1e30f;
    for (int j = t; j < N_TOK; j += 256) { simr[j] *= 0.125f; m = fmaxf(m, simr[j]); }
    m = blockReduceMax(m, red);
    float s = 0.f;
    for (int j = t; j < N_TOK; j += 256) s += __expf(simr[j] - m);
    s = blockReduceSum(s, red);
    float inv = 1.f / s;
    float tot = 0.f;
    for (int j = t; j < N_TOK; j += 256) {
        float p = __expf(simr[j] - m) * inv;
        float keep = (raw[(size_t)i * N_TOK + j] * 0.125f > 0.75f) ? 1.f : 0.f;
        float v = p * keep;
        simr[j] = v;
        tot += v;
    }
    tot = blockReduceSum(tot, red);
    float invt = 1.f / (tot + 1e-8f);
    for (int j = t; j < N_TOK; j += 256) out_sim[(size_t)i * N_TOK + j] = simr[j] * invt;
}

// ---------------- AV:  x[i][h*32+d] = sum_j attn[h][i][j] * v[j][h*32+d] ----------------
__global__ void av_gemm(const float* __restrict__ attn, const float* __restrict__ yc,
                        float* __restrict__ out) {
    int h = blockIdx.y;
    int i0 = blockIdx.x * 64;
    const float* Ah = attn + (size_t)h * N_TOK * N_TOK;
    __shared__ float As[64][33];
    __shared__ float Bs[32][33];
    int tid = threadIdx.x;
    int ty = tid >> 5;     // 0..7 (row group)
    int tx = tid & 31;     // 0..31 (head dim)
    float acc[8] = {};
    for (int j0 = 0; j0 < N_TOK; j0 += 32) {
        int kw = N_TOK - j0; if (kw > 32) kw = 32;
        #pragma unroll
        for (int p = 0; p < 8; ++p) {
            int idx = tid + p * 256;
            int r = idx >> 5, k = idx & 31;
            int gi = i0 + r;
            As[r][k] = (gi < N_TOK && k < kw) ? Ah[(size_t)gi * N_TOK + j0 + k] : 0.f;
        }
        #pragma unroll
        for (int p = 0; p < 4; ++p) {
            int idx = tid + p * 256;
            int k = idx >> 5, d = idx & 31;
            Bs[k][d] = (k < kw) ? yc[(size_t)(j0 + k) * C3 + 512 + h * HD + d] : 0.f;
        }
        __syncthreads();
        #pragma unroll
        for (int k = 0; k < 32; ++k) {
            float bv = Bs[k][tx];
            #pragma unroll
            for (int r = 0; r < 8; ++r) acc[r] += As[ty + r * 8][k] * bv;
        }
        __syncthreads();
    }
    #pragma unroll
    for (int r = 0; r < 8; ++r) {
        int gi = i0 + ty + r * 8;
        if (gi < N_TOK) out[(size_t)gi * 512 + h * HD + tx] = acc[r];
    }
}

// ---------------- launch ----------------
extern "C" void kernel_launch(void* const* d_in, const int* in_sizes, int n_in,
                              void* d_out, int out_size) {
    const float* x_cls = (const float*)d_in[0];
    const float* x_reg = (const float*)d_in[1];
    const float* Wc    = (const float*)d_in[2];
    const float* Wr    = (const float*)d_in[3];
    float* out     = (float*)d_out;
    float* out_sim = out + (size_t)N_TOK * 512;

    float *yc, *yr, *qnc, *knc, *qnr, *knr, *vn, *S, *raw;
    cudaGetSymbolAddress((void**)&yc,  g_yc);
    cudaGetSymbolAddress((void**)&yr,  g_yr);
    cudaGetSymbolAddress((void**)&qnc, g_qnc);
    cudaGetSymbolAddress((void**)&knc, g_knc);
    cudaGetSymbolAddress((void**)&qnr, g_qnr);
    cudaGetSymbolAddress((void**)&knr, g_knr);
    cudaGetSymbolAddress((void**)&vn,  g_vn);
    cudaGetSymbolAddress((void**)&S,   g_S);
    cudaGetSymbolAddress((void**)&raw, g_raw);

    // 1) QKV projections
    sgemm_nn<<<dim3(12, 32), 256>>>(x_cls, Wc, yc, N_TOK, C3, C_DIM, C_DIM, C3, C3);
    sgemm_nn<<<dim3(12, 32), 256>>>(x_reg, Wr, yr, N_TOK, C3, C_DIM, C_DIM, C3, C3);

    // 2) per-head L2 normalize (+ write x_ori half of out)
    normalize_kernel<<<N_TOK, 256>>>(yc, yr, out);

    // 3) scores (alpha=25) and raw = vn.vn^T
    long long cz = (long long)N_TOK * N_TOK;
    sgemm_nt<<<dim3(32, 32, 8), 256>>>(qnc, knc, S,            N_TOK, N_TOK, 32,  C_DIM, C_DIM, N_TOK, 32, 32, cz, 25.0f);
    sgemm_nt<<<dim3(32, 32, 8), 256>>>(qnr, knr, S + 8ULL * cz, N_TOK, N_TOK, 32,  C_DIM, C_DIM, N_TOK, 32, 32, cz, 25.0f);
    sgemm_nt<<<dim3(32, 32, 1), 256>>>(vn,  vn,  raw,          N_TOK, N_TOK, 256, C_DIM, C_DIM, N_TOK, 0,  0,  0,  1.0f);

    // 4) softmax + combine + block mask + sim_round2   (attn overwrites cls half of S)
    softmax_combine<<<N_TOK, 256>>>(S, raw, out_sim);

    // 5) x = attn @ v   (first half of out)
    av_gemm<<<dim3(32, 8), 256>>>(S, yc, out);
}